// round 7
// baseline (speedup 1.0000x reference)
#include <cuda_runtime.h>
#include <cuda_fp16.h>
#include <math.h>
#include <stdint.h>

// ---------------- problem constants ----------------
#define BATCH 512
#define HDIM  2048
#define BH    (BATCH * HDIM)       // 1,048,576
#define ACT   (BATCH * HDIM)
#define KTOT  4096

// ---------------- GEMM tiling ----------------
#define BM 128
#define BN 128
#define BK 32
#define NITER (KTOT / BK)          // 128

// smem layout
#define A_STRIDE 40                 // halves per A row
#define B_STRIDE 136                // halves per fp16-B row
#define RAW_STRIDE 132              // floats per raw-B row
#define A_TILE_B   (128 * A_STRIDE * 2)     // 10240
#define RAW_TILE_B (BK * RAW_STRIDE * 4)    // 16896
#define B16_TILE_B (BK * B_STRIDE * 2)      // 8704
#define OFF_A   0                            // 4 stages
#define OFF_RAW (4 * A_TILE_B)               // 40960, 3 stages
#define OFF_B16 (OFF_RAW + 3 * RAW_TILE_B)   // 91648, 2 stages
#define DYN_SMEM (OFF_B16 + 2 * B16_TILE_B)  // 109056

// ---------------- device scratch ----------------
__device__ float g_Z[4ull * BH];                 // 16 MB
__device__ __half g_A[2ull * ACT];               // [phase][B][2048] fp16

// ---------------- PTX helpers ----------------
__device__ __forceinline__ uint32_t s2u(const void* p) {
    uint32_t a;
    asm("{ .reg .u64 t; cvta.to.shared.u64 t, %1; cvt.u32.u64 %0, t; }"
        : "=r"(a) : "l"(p));
    return a;
}
__device__ __forceinline__ void cp16(uint32_t dst, const void* src) {
    asm volatile("cp.async.cg.shared.global [%0], [%1], 16;" :: "r"(dst), "l"(src));
}
#define LDSM4(R, addr)                                                        \
    asm volatile("ldmatrix.sync.aligned.m8n8.x4.shared.b16 {%0,%1,%2,%3}, [%4];" \
                 : "=r"((R)[0]), "=r"((R)[1]), "=r"((R)[2]), "=r"((R)[3])     \
                 : "r"(addr))
#define LDSM4T(R, addr)                                                       \
    asm volatile("ldmatrix.sync.aligned.m8n8.x4.trans.shared.b16 {%0,%1,%2,%3}, [%4];" \
                 : "=r"((R)[0]), "=r"((R)[1]), "=r"((R)[2]), "=r"((R)[3])     \
                 : "r"(addr))
#define MMA(D, A, B0, B1)                                                     \
    asm volatile("mma.sync.aligned.m16n8k16.row.col.f32.f16.f16.f32 "          \
                 "{%0,%1,%2,%3},{%4,%5,%6,%7},{%8,%9},{%0,%1,%2,%3};"          \
                 : "+f"((D)[0]), "+f"((D)[1]), "+f"((D)[2]), "+f"((D)[3])     \
                 : "r"((A)[0]), "r"((A)[1]), "r"((A)[2]), "r"((A)[3]),        \
                   "r"(B0), "r"(B1))

// ---------------- activation conversion ----------------
__global__ void convert_acts(const float* __restrict__ X,
                             const float* __restrict__ S) {
    size_t i4 = ((size_t)blockIdx.x * blockDim.x + threadIdx.x) * 4;
    const float* src = (i4 < ACT) ? (X + i4) : (S + (i4 - ACT));
    float4 v = *reinterpret_cast<const float4*>(src);
    __half h[4];
    h[0] = __float2half(v.x); h[1] = __float2half(v.y);
    h[2] = __float2half(v.z); h[3] = __float2half(v.w);
    *reinterpret_cast<uint2*>(&g_A[i4]) = *reinterpret_cast<uint2*>(h);
}

// ---------------- fused GEMM (128 threads, 4 warps of 64x64) ----------------
__device__ __forceinline__ void prefetch(uint32_t sb, int tid,
                                         const float* Wp, const float* Up,
                                         int bm, int bn, int c) {
    int k0 = c * BK;
    int phase = k0 >> 11;
    int kk = k0 & 2047;
    const __half* A_p = g_A + (size_t)phase * ACT + (size_t)bm * 2048 + kk;
    const float* B_p = (phase ? Up : Wp) + (size_t)kk * 2048 + bn;

    uint32_t a_st = sb + OFF_A   + (uint32_t)(c & 3) * A_TILE_B;
    uint32_t r_st = sb + OFF_RAW + (uint32_t)(c % 3) * RAW_TILE_B;

    // A tile fp16: 128 rows x 4 chunks(16B) = 512; 4 per thread
    #pragma unroll
    for (int t = 0; t < 4; t++) {
        int cid = tid + t * 128;
        int r = cid >> 2, cc = cid & 3;
        cp16(a_st + (uint32_t)(r * (A_STRIDE * 2) + cc * 16),
             A_p + (size_t)r * 2048 + cc * 8);
    }
    // raw B tile fp32: 32 rows x 32 chunks(16B) = 1024; 8 per thread
    #pragma unroll
    for (int t = 0; t < 8; t++) {
        int cid = tid + t * 128;
        int r = cid >> 5, cc = cid & 31;
        cp16(r_st + (uint32_t)(r * (RAW_STRIDE * 4) + cc * 16),
             B_p + (size_t)r * 2048 + cc * 4);
    }
}

// Convert one raw fp32 B tile (32x128) to fp16 padded layout.
// thread t: row = t>>2, 32 cols starting at (t&3)*32.
__device__ __forceinline__ void convert_tile(uint32_t raw, uint32_t dst16, int tid) {
    int r  = tid >> 2;
    int cg = tid & 3;
    uint32_t src = raw   + (uint32_t)(r * (RAW_STRIDE * 4) + cg * 128);
    uint32_t dst = dst16 + (uint32_t)(r * (B_STRIDE * 2)   + cg * 64);
    #pragma unroll
    for (int s = 0; s < 4; s++) {
        float4 f0, f1;
        asm volatile("ld.shared.v4.f32 {%0,%1,%2,%3}, [%4];"
                     : "=f"(f0.x), "=f"(f0.y), "=f"(f0.z), "=f"(f0.w)
                     : "r"(src + (uint32_t)(s * 32)));
        asm volatile("ld.shared.v4.f32 {%0,%1,%2,%3}, [%4];"
                     : "=f"(f1.x), "=f"(f1.y), "=f"(f1.z), "=f"(f1.w)
                     : "r"(src + (uint32_t)(s * 32 + 16)));
        __half2 h0 = __floats2half2_rn(f0.x, f0.y);
        __half2 h1 = __floats2half2_rn(f0.z, f0.w);
        __half2 h2 = __floats2half2_rn(f1.x, f1.y);
        __half2 h3 = __floats2half2_rn(f1.z, f1.w);
        asm volatile("st.shared.v4.b32 [%0], {%1,%2,%3,%4};"
                     :: "r"(dst + (uint32_t)(s * 16)),
                        "r"(*(uint32_t*)&h0), "r"(*(uint32_t*)&h1),
                        "r"(*(uint32_t*)&h2), "r"(*(uint32_t*)&h3)
                     : "memory");
    }
}

__global__ __launch_bounds__(128, 2) void gemm_mma(
    const float* __restrict__ Wi, const float* __restrict__ Ui,
    const float* __restrict__ Wf, const float* __restrict__ Uf,
    const float* __restrict__ Wg, const float* __restrict__ Ug,
    const float* __restrict__ Wc, const float* __restrict__ Uc)
{
    extern __shared__ char smem[];
    const uint32_t sb = s2u(smem);
    const int tid  = threadIdx.x;
    const int gate = blockIdx.z;
    const int bm   = blockIdx.y * BM;
    const int bn   = blockIdx.x * BN;

    const float* Wp; const float* Up;
    switch (gate) {
        case 0:  Wp = Wi; Up = Ui; break;
        case 1:  Wp = Wf; Up = Uf; break;
        case 2:  Wp = Wg; Up = Ug; break;
        default: Wp = Wc; Up = Uc; break;
    }

    const int warp = tid >> 5;
    const int lane = tid & 31;
    const int wm = warp >> 1;        // 0..1 -> m offset 64*wm
    const int wn = warp & 1;         // 0..1 -> n offset 64*wn
    const int lr  = lane & 15;
    const int lc8 = (lane >> 4) * 8;

    float acc[4][8][4];
    #pragma unroll
    for (int i = 0; i < 4; i++)
        #pragma unroll
        for (int j = 0; j < 8; j++)
            #pragma unroll
            for (int k = 0; k < 4; k++) acc[i][j][k] = 0.0f;

    uint32_t a_lane = (uint32_t)((wm * 64 + lr) * (A_STRIDE * 2) + lc8 * 2);
    uint32_t b_lane = (uint32_t)(lr * (B_STRIDE * 2) + (wn * 64 + lc8) * 2);

    // prologue: chunks 0,1,2 in flight; convert chunk 0
    prefetch(sb, tid, Wp, Up, bm, bn, 0);
    asm volatile("cp.async.commit_group;" ::: "memory");
    prefetch(sb, tid, Wp, Up, bm, bn, 1);
    asm volatile("cp.async.commit_group;" ::: "memory");
    prefetch(sb, tid, Wp, Up, bm, bn, 2);
    asm volatile("cp.async.commit_group;" ::: "memory");

    asm volatile("cp.async.wait_group 2;" ::: "memory");
    __syncthreads();
    convert_tile(sb + OFF_RAW, sb + OFF_B16, tid);   // chunk 0 -> fp16 buf 0

    #pragma unroll 1
    for (int c = 0; c < NITER; c++) {
        if (c + 2 < NITER) {
            asm volatile("cp.async.wait_group 1;" ::: "memory");
        } else {
            asm volatile("cp.async.wait_group 0;" ::: "memory");
        }
        __syncthreads();

        if (c + 3 < NITER)
            prefetch(sb, tid, Wp, Up, bm, bn, c + 3);
        asm volatile("cp.async.commit_group;" ::: "memory");

        if (c + 1 < NITER)
            convert_tile(sb + OFF_RAW + (uint32_t)((c + 1) % 3) * RAW_TILE_B,
                         sb + OFF_B16 + (uint32_t)((c + 1) & 1) * B16_TILE_B,
                         tid);

        // compute chunk c
        uint32_t ast = sb + OFF_A   + (uint32_t)(c & 3) * A_TILE_B;
        uint32_t bst = sb + OFF_B16 + (uint32_t)(c & 1) * B16_TILE_B;
        #pragma unroll
        for (int kf = 0; kf < 2; kf++) {
            uint32_t aoff = ast + a_lane + (uint32_t)(kf * 32);
            uint32_t boff = bst + b_lane + (uint32_t)(kf * 16 * B_STRIDE * 2);

            uint32_t ar[4][4], br[4][4];
            #pragma unroll
            for (int mf = 0; mf < 4; mf++)
                LDSM4(ar[mf], aoff + (uint32_t)(mf * 16 * A_STRIDE * 2));
            #pragma unroll
            for (int nf2 = 0; nf2 < 4; nf2++)
                LDSM4T(br[nf2], boff + (uint32_t)(nf2 * 32));

            #pragma unroll
            for (int mf = 0; mf < 4; mf++)
                #pragma unroll
                for (int nf = 0; nf < 8; nf++)
                    MMA(acc[mf][nf], ar[mf], br[nf >> 1][(nf & 1) * 2],
                        br[nf >> 1][(nf & 1) * 2 + 1]);
        }
    }

    // store accumulators to g_Z
    float* Zg = g_Z + (size_t)gate * BH;
    const int gr = lane >> 2;
    const int gc = (lane & 3) * 2;
    #pragma unroll
    for (int mf = 0; mf < 4; mf++) {
        #pragma unroll
        for (int nf = 0; nf < 8; nf++) {
            int row = bm + wm * 64 + mf * 16 + gr;
            int col = bn + wn * 64 + nf * 8 + gc;
            *reinterpret_cast<float2*>(&Zg[(size_t)row * HDIM + col]) =
                make_float2(acc[mf][nf][0], acc[mf][nf][1]);
            *reinterpret_cast<float2*>(&Zg[(size_t)(row + 8) * HDIM + col]) =
                make_float2(acc[mf][nf][2], acc[mf][nf][3]);
        }
    }
}

// ---------------- fused gate epilogue ----------------
__device__ __forceinline__ float sigmoidf_(float x) {
    return 1.0f / (1.0f + __expf(-x));
}

__global__ void lstm_epilogue(const float* __restrict__ bi,
                              const float* __restrict__ bf,
                              const float* __restrict__ bg,
                              const float* __restrict__ bc,
                              const float* __restrict__ prevout,
                              float* __restrict__ out, int out_size) {
    int idx = blockIdx.x * blockDim.x + threadIdx.x;
    if (idx >= BH) return;
    int h = idx & (HDIM - 1);

    float zi = g_Z[0 * (size_t)BH + idx] + bi[h];
    float zf = g_Z[1 * (size_t)BH + idx] + bf[h];
    float zg = g_Z[2 * (size_t)BH + idx] + bg[h];
    float zc = g_Z[3 * (size_t)BH + idx] + bc[h];

    float ig = sigmoidf_(zi);
    float fg = sigmoidf_(zf);
    float gg = sigmoidf_(zg);   // reference quirk: sigmoid for g
    float cc = tanhf(zc);

    float c = fg * prevout[idx] + ig * cc;
    float state = gg * tanhf(c);

    if (out_size >= 3 * BH) {
        out[idx]          = c;
        out[BH + idx]     = state;
        out[2 * BH + idx] = c;
    } else if (out_size >= 2 * BH) {
        out[idx]      = state;
        out[BH + idx] = c;
    } else {
        out[idx] = c;
    }
}

// ---------------- launcher ----------------
extern "C" void kernel_launch(void* const* d_in, const int* in_sizes, int n_in,
                              void* d_out, int out_size) {
    const float* inputs = (const float*)d_in[0];
    const float* states = (const float*)d_in[1];
    const float* Wi = (const float*)d_in[2];
    const float* Ui = (const float*)d_in[3];
    const float* bi = (const float*)d_in[4];
    const float* Wf = (const float*)d_in[5];
    const float* Uf = (const float*)d_in[6];
    const float* bf = (const float*)d_in[7];
    const float* Wg = (const float*)d_in[8];
    const float* Ug = (const float*)d_in[9];
    const float* bg = (const float*)d_in[10];
    const float* Wc = (const float*)d_in[11];
    const float* Uc = (const float*)d_in[12];
    const float* bc = (const float*)d_in[13];

    const float* prevstate = states;        // states[0]
    const float* prevout   = states + BH;   // states[1]

    cudaFuncSetAttribute(gemm_mma, cudaFuncAttributeMaxDynamicSharedMemorySize,
                         DYN_SMEM);

    convert_acts<<<(2 * ACT) / (256 * 4), 256>>>(inputs, prevstate);

    dim3 ggrid(HDIM / BN, BATCH / BM, 4);   // (16, 4, 4) = 256 CTAs
    gemm_mma<<<ggrid, 128, DYN_SMEM>>>(Wi, Ui, Wf, Uf, Wg, Ug, Wc, Uc);

    lstm_epilogue<<<(BH + 255) / 256, 256>>>(bi, bf, bg, bc, prevout,
                                             (float*)d_out, out_size);
}

// round 8
// speedup vs baseline: 1.2246x; 1.2246x over previous
#include <cuda_runtime.h>
#include <cuda_fp16.h>
#include <math.h>
#include <stdint.h>

// ---------------- problem constants ----------------
#define BATCH 512
#define HDIM  2048
#define BH    (BATCH * HDIM)       // 1,048,576
#define ACT   (BATCH * HDIM)
#define WELEM (2048 * 2048)
#define KTOT  4096

// ---------------- GEMM tiling ----------------
#define BM 128
#define BN 128
#define BK 32
#define NITER (KTOT / BK)          // 128

// smem layout (fp16 elems): A padded stride 40, B padded stride 136
#define A_STRIDE 40
#define B_STRIDE 136
#define A_TILE_B (128 * A_STRIDE * 2)   // 10240 B
#define B_TILE_B (BK * B_STRIDE * 2)    // 8704 B
#define OFF_A 0
#define OFF_B (A_TILE_B)
#define STAGE_B (A_TILE_B + B_TILE_B)   // 18944
#define NSTAGE 4
#define DYN_SMEM (NSTAGE * STAGE_B)     // 75776

// ---------------- device scratch ----------------
__device__ float g_Z[4ull * BH];                 // 16 MB
__device__ __half g_A[2ull * ACT];               // [phase][B][2048] fp16
__device__ __half g_B[8ull * WELEM];             // [gate*2+phase][K][N] fp16

// ---------------- PTX helpers ----------------
__device__ __forceinline__ uint32_t s2u(const void* p) {
    uint32_t a;
    asm("{ .reg .u64 t; cvta.to.shared.u64 t, %1; cvt.u32.u64 %0, t; }"
        : "=r"(a) : "l"(p));
    return a;
}
__device__ __forceinline__ void cp16(uint32_t dst, const void* src) {
    asm volatile("cp.async.cg.shared.global [%0], [%1], 16;" :: "r"(dst), "l"(src));
}
#define LDSM4(R, addr)                                                        \
    asm volatile("ldmatrix.sync.aligned.m8n8.x4.shared.b16 {%0,%1,%2,%3}, [%4];" \
                 : "=r"((R)[0]), "=r"((R)[1]), "=r"((R)[2]), "=r"((R)[3])     \
                 : "r"(addr))
#define LDSM4T(R, addr)                                                       \
    asm volatile("ldmatrix.sync.aligned.m8n8.x4.trans.shared.b16 {%0,%1,%2,%3}, [%4];" \
                 : "=r"((R)[0]), "=r"((R)[1]), "=r"((R)[2]), "=r"((R)[3])     \
                 : "r"(addr))
#define MMA(D, A, B0, B1)                                                     \
    asm volatile("mma.sync.aligned.m16n8k16.row.col.f32.f16.f16.f32 "          \
                 "{%0,%1,%2,%3},{%4,%5,%6,%7},{%8,%9},{%0,%1,%2,%3};"          \
                 : "+f"((D)[0]), "+f"((D)[1]), "+f"((D)[2]), "+f"((D)[3])     \
                 : "r"((A)[0]), "r"((A)[1]), "r"((A)[2]), "r"((A)[3]),        \
                   "r"(B0), "r"(B1))

// ---------------- conversion kernels ----------------
__global__ void convert_acts(const float* __restrict__ X,
                             const float* __restrict__ S) {
    size_t i4 = ((size_t)blockIdx.x * blockDim.x + threadIdx.x) * 4;
    const float* src = (i4 < ACT) ? (X + i4) : (S + (i4 - ACT));
    float4 v = *reinterpret_cast<const float4*>(src);
    __half h[4];
    h[0] = __float2half(v.x); h[1] = __float2half(v.y);
    h[2] = __float2half(v.z); h[3] = __float2half(v.w);
    *reinterpret_cast<uint2*>(&g_A[i4]) = *reinterpret_cast<uint2*>(h);
}

// 16 floats per thread for deeper MLP; 1024 blocks x 8 matrices
__global__ void convert_w(const float* Wi, const float* Ui,
                          const float* Wf, const float* Uf,
                          const float* Wg, const float* Ug,
                          const float* Wc, const float* Uc) {
    int mat = blockIdx.y;
    const float* src;
    switch (mat) {
        case 0: src = Wi; break; case 1: src = Ui; break;
        case 2: src = Wf; break; case 3: src = Uf; break;
        case 4: src = Wg; break; case 5: src = Ug; break;
        case 6: src = Wc; break; default: src = Uc; break;
    }
    size_t base = ((size_t)blockIdx.x * blockDim.x + threadIdx.x) * 16;
    size_t o = (size_t)mat * WELEM + base;
    float4 v[4];
    #pragma unroll
    for (int t = 0; t < 4; t++)
        v[t] = *reinterpret_cast<const float4*>(src + base + t * 4);
    #pragma unroll
    for (int t = 0; t < 4; t++) {
        __half h[4];
        h[0] = __float2half(v[t].x); h[1] = __float2half(v[t].y);
        h[2] = __float2half(v[t].z); h[3] = __float2half(v[t].w);
        *reinterpret_cast<uint2*>(&g_B[o + t * 4]) = *reinterpret_cast<uint2*>(h);
    }
}

// ---------------- mma.sync GEMM (128 threads, 4 warps of 64x64) ----------------
__device__ __forceinline__ void prefetch(uint32_t stage, int tid,
                                         int gate, int bm, int bn, int c) {
    int k0 = c * BK;
    int phase = k0 >> 11;
    int kk = k0 & 2047;
    const __half* A_p = g_A + (size_t)phase * ACT + (size_t)bm * 2048 + kk;
    const __half* B_p = g_B + (size_t)(gate * 2 + phase) * WELEM
                            + (size_t)kk * 2048 + bn;

    // A tile: 128 rows x 4 chunks(16B) = 512; 4 per thread
    #pragma unroll
    for (int t = 0; t < 4; t++) {
        int cid = tid + t * 128;
        int r = cid >> 2, cc = cid & 3;
        cp16(stage + OFF_A + (uint32_t)(r * (A_STRIDE * 2) + cc * 16),
             A_p + (size_t)r * 2048 + cc * 8);
    }
    // B tile: 32 rows x 16 chunks = 512; 4 per thread
    #pragma unroll
    for (int t = 0; t < 4; t++) {
        int cid = tid + t * 128;
        int r = cid >> 4, cc = cid & 15;
        cp16(stage + OFF_B + (uint32_t)(r * (B_STRIDE * 2) + cc * 16),
             B_p + (size_t)r * 2048 + cc * 8);
    }
}

__global__ __launch_bounds__(128, 2) void gemm_mma() {
    extern __shared__ char smem[];
    const uint32_t sb = s2u(smem);
    const int tid  = threadIdx.x;
    const int gate = blockIdx.z;
    const int bm   = blockIdx.y * BM;
    const int bn   = blockIdx.x * BN;

    const int warp = tid >> 5;
    const int lane = tid & 31;
    const int wm = warp >> 1;        // 0..1 -> m offset 64*wm
    const int wn = warp & 1;         // 0..1 -> n offset 64*wn
    const int lr  = lane & 15;
    const int lc8 = (lane >> 4) * 8;

    float acc[4][8][4];
    #pragma unroll
    for (int i = 0; i < 4; i++)
        #pragma unroll
        for (int j = 0; j < 8; j++)
            #pragma unroll
            for (int k = 0; k < 4; k++) acc[i][j][k] = 0.0f;

    uint32_t a_lane = (uint32_t)((wm * 64 + lr) * (A_STRIDE * 2) + lc8 * 2);
    uint32_t b_lane = (uint32_t)(lr * (B_STRIDE * 2) + (wn * 64 + lc8) * 2);

    // 4-stage prologue: chunks 0,1,2 in flight
    prefetch(sb + 0 * STAGE_B, tid, gate, bm, bn, 0);
    asm volatile("cp.async.commit_group;" ::: "memory");
    prefetch(sb + 1 * STAGE_B, tid, gate, bm, bn, 1);
    asm volatile("cp.async.commit_group;" ::: "memory");
    prefetch(sb + 2 * STAGE_B, tid, gate, bm, bn, 2);
    asm volatile("cp.async.commit_group;" ::: "memory");

    #pragma unroll 1
    for (int c = 0; c < NITER; c++) {
        asm volatile("cp.async.wait_group 2;" ::: "memory");
        __syncthreads();   // single sync: orders buffer reuse (see distance-3 argument)

        if (c + 3 < NITER)
            prefetch(sb + (uint32_t)((c + 3) & 3) * STAGE_B, tid, gate, bm, bn, c + 3);
        asm volatile("cp.async.commit_group;" ::: "memory");

        uint32_t st = sb + (uint32_t)(c & 3) * STAGE_B;
        #pragma unroll
        for (int kf = 0; kf < 2; kf++) {
            uint32_t aoff = st + OFF_A + a_lane + (uint32_t)(kf * 32);
            uint32_t boff = st + OFF_B + b_lane + (uint32_t)(kf * 16 * B_STRIDE * 2);

            uint32_t ar[4][4], br[4][4];
            #pragma unroll
            for (int mf = 0; mf < 4; mf++)
                LDSM4(ar[mf], aoff + (uint32_t)(mf * 16 * A_STRIDE * 2));
            #pragma unroll
            for (int nf2 = 0; nf2 < 4; nf2++)
                LDSM4T(br[nf2], boff + (uint32_t)(nf2 * 32));

            #pragma unroll
            for (int mf = 0; mf < 4; mf++)
                #pragma unroll
                for (int nf = 0; nf < 8; nf++)
                    MMA(acc[mf][nf], ar[mf], br[nf >> 1][(nf & 1) * 2],
                        br[nf >> 1][(nf & 1) * 2 + 1]);
        }
    }

    // store accumulators to g_Z
    float* Zg = g_Z + (size_t)gate * BH;
    const int gr = lane >> 2;
    const int gc = (lane & 3) * 2;
    #pragma unroll
    for (int mf = 0; mf < 4; mf++) {
        #pragma unroll
        for (int nf = 0; nf < 8; nf++) {
            int row = bm + wm * 64 + mf * 16 + gr;
            int col = bn + wn * 64 + nf * 8 + gc;
            *reinterpret_cast<float2*>(&Zg[(size_t)row * HDIM + col]) =
                make_float2(acc[mf][nf][0], acc[mf][nf][1]);
            *reinterpret_cast<float2*>(&Zg[(size_t)(row + 8) * HDIM + col]) =
                make_float2(acc[mf][nf][2], acc[mf][nf][3]);
        }
    }
}

// ---------------- fused gate epilogue (vectorized) ----------------
__device__ __forceinline__ float sigmoidf_(float x) {
    return 1.0f / (1.0f + __expf(-x));
}

__global__ void lstm_epilogue(const float* __restrict__ bi,
                              const float* __restrict__ bf,
                              const float* __restrict__ bg,
                              const float* __restrict__ bc,
                              const float* __restrict__ prevout,
                              float* __restrict__ out, int out_size) {
    int idx = (blockIdx.x * blockDim.x + threadIdx.x) * 4;
    if (idx >= BH) return;
    int h = idx & (HDIM - 1);

    float4 zi = *reinterpret_cast<const float4*>(&g_Z[0 * (size_t)BH + idx]);
    float4 zf = *reinterpret_cast<const float4*>(&g_Z[1 * (size_t)BH + idx]);
    float4 zg = *reinterpret_cast<const float4*>(&g_Z[2 * (size_t)BH + idx]);
    float4 zc = *reinterpret_cast<const float4*>(&g_Z[3 * (size_t)BH + idx]);
    float4 po = *reinterpret_cast<const float4*>(&prevout[idx]);
    float4 vbi = *reinterpret_cast<const float4*>(&bi[h]);
    float4 vbf = *reinterpret_cast<const float4*>(&bf[h]);
    float4 vbg = *reinterpret_cast<const float4*>(&bg[h]);
    float4 vbc = *reinterpret_cast<const float4*>(&bc[h]);

    float c4[4], s4[4];
    float zis[4] = {zi.x, zi.y, zi.z, zi.w};
    float zfs[4] = {zf.x, zf.y, zf.z, zf.w};
    float zgs[4] = {zg.x, zg.y, zg.z, zg.w};
    float zcs[4] = {zc.x, zc.y, zc.z, zc.w};
    float pos[4] = {po.x, po.y, po.z, po.w};
    float bis[4] = {vbi.x, vbi.y, vbi.z, vbi.w};
    float bfs[4] = {vbf.x, vbf.y, vbf.z, vbf.w};
    float bgs[4] = {vbg.x, vbg.y, vbg.z, vbg.w};
    float bcs[4] = {vbc.x, vbc.y, vbc.z, vbc.w};

    #pragma unroll
    for (int j = 0; j < 4; j++) {
        float ig = sigmoidf_(zis[j] + bis[j]);
        float fg = sigmoidf_(zfs[j] + bfs[j]);
        float gg = sigmoidf_(zgs[j] + bgs[j]);   // reference quirk: sigmoid for g
        float cc = tanhf(zcs[j] + bcs[j]);
        c4[j] = fg * pos[j] + ig * cc;
        s4[j] = gg * tanhf(c4[j]);
    }

    float4 cv = make_float4(c4[0], c4[1], c4[2], c4[3]);
    float4 sv = make_float4(s4[0], s4[1], s4[2], s4[3]);

    if (out_size >= 3 * BH) {
        *reinterpret_cast<float4*>(&out[idx])          = cv;
        *reinterpret_cast<float4*>(&out[BH + idx])     = sv;
        *reinterpret_cast<float4*>(&out[2 * BH + idx]) = cv;
    } else if (out_size >= 2 * BH) {
        *reinterpret_cast<float4*>(&out[idx])      = sv;
        *reinterpret_cast<float4*>(&out[BH + idx]) = cv;
    } else {
        *reinterpret_cast<float4*>(&out[idx]) = cv;
    }
}

// ---------------- launcher ----------------
extern "C" void kernel_launch(void* const* d_in, const int* in_sizes, int n_in,
                              void* d_out, int out_size) {
    const float* inputs = (const float*)d_in[0];
    const float* states = (const float*)d_in[1];
    const float* Wi = (const float*)d_in[2];
    const float* Ui = (const float*)d_in[3];
    const float* bi = (const float*)d_in[4];
    const float* Wf = (const float*)d_in[5];
    const float* Uf = (const float*)d_in[6];
    const float* bf = (const float*)d_in[7];
    const float* Wg = (const float*)d_in[8];
    const float* Ug = (const float*)d_in[9];
    const float* bg = (const float*)d_in[10];
    const float* Wc = (const float*)d_in[11];
    const float* Uc = (const float*)d_in[12];
    const float* bc = (const float*)d_in[13];

    const float* prevstate = states;        // states[0]
    const float* prevout   = states + BH;   // states[1]

    cudaFuncSetAttribute(gemm_mma, cudaFuncAttributeMaxDynamicSharedMemorySize,
                         DYN_SMEM);

    convert_acts<<<(2 * ACT) / (256 * 4), 256>>>(inputs, prevstate);

    dim3 wgrid(WELEM / (256 * 16), 8);   // (1024, 8)
    convert_w<<<wgrid, 256>>>(Wi, Ui, Wf, Uf, Wg, Ug, Wc, Uc);

    dim3 ggrid(HDIM / BN, BATCH / BM, 4);   // (16, 4, 4) = 256 CTAs
    gemm_mma<<<ggrid, 128, DYN_SMEM>>>();

    lstm_epilogue<<<BH / (256 * 4), 256>>>(bi, bf, bg, bc, prevout,
                                           (float*)d_out, out_size);
}